// round 16
// baseline (speedup 1.0000x reference)
#include <cuda_runtime.h>
#include <cuda_fp16.h>
#include <cstdint>
#include <math.h>

#define DIM_IN 2048
#define QDIM   2048
#define LATENT 1024
#define N_ROIS 4096
#define N_BANK 8192
#define LN_EPS 1e-5f

// ============================ static scratch ====================================
__device__ __half g_feat_h[(size_t)N_ROIS * QDIM];
__device__ __half g_kb_h[(size_t)N_BANK * DIM_IN];
#define WSZ ((size_t)LATENT * QDIM)
__device__ __half g_W_h[7 * WSZ];
__device__ __half g_Q_h[(size_t)2 * N_ROIS * LATENT];
__device__ __half g_K_h[(size_t)2 * N_BANK * LATENT];
__device__ __half g_Vt_h[(size_t)2 * LATENT * N_BANK];
__device__ __half g_E_h[(size_t)2 * N_ROIS * N_BANK];
__device__ float  g_F  [(size_t)2 * N_ROIS * LATENT];
__device__ __half g_X_h[(size_t)N_ROIS * LATENT];
__device__ float g_rsum[2 * N_ROIS];

// ============================ PTX helpers =======================================
__device__ __forceinline__ uint32_t smem_u32(const void* p) {
    uint32_t a;
    asm("{ .reg .u64 t; cvta.to.shared.u64 t, %1; cvt.u32.u64 %0, t; }" : "=r"(a) : "l"(p));
    return a;
}
__device__ __forceinline__ void cp_async16(uint32_t s, const void* g) {
    asm volatile("cp.async.cg.shared.global [%0], [%1], 16;\n" :: "r"(s), "l"(g));
}
#define CP_COMMIT() asm volatile("cp.async.commit_group;\n" ::: "memory")
#define CP_WAIT1()  asm volatile("cp.async.wait_group 1;\n" ::: "memory")

#define LDSM_X4(r, a)                                                               \
    asm volatile("ldmatrix.sync.aligned.m8n8.x4.shared.b16 {%0,%1,%2,%3}, [%4];"    \
        : "=r"((r)[0]), "=r"((r)[1]), "=r"((r)[2]), "=r"((r)[3]) : "r"(a))

#define MMA_F16(c, a, b0, b1)                                                       \
    asm volatile("mma.sync.aligned.m16n8k16.row.col.f32.f16.f16.f32 "               \
        "{%0,%1,%2,%3}, {%4,%5,%6,%7}, {%8,%9}, {%0,%1,%2,%3};"                     \
        : "+f"((c)[0]), "+f"((c)[1]), "+f"((c)[2]), "+f"((c)[3])                    \
        : "r"((a)[0]), "r"((a)[1]), "r"((a)[2]), "r"((a)[3]), "r"(b0), "r"(b1))

// ============================ common GEMM pieces ================================
// Block 128x256x64, 16 warps (512 thr), warp tile 32x64 (4M x 4N warp grid),
// 3-stage cp.async, single-term fp16. smem rows padded to 144 B.
#define ROW_B    144
#define A_TILE_B (128 * ROW_B)            // 18432
#define B_TILE_B (256 * ROW_B)            // 36864
#define STAGE_B  (A_TILE_B + B_TILE_B)    // 55296
#define SMEM_G   (3 * STAGE_B)            // 165888

__device__ __forceinline__ void load_stage_g(uint32_t st,
    const __half* __restrict__ Ah, int lda, int m0,
    const __half* __restrict__ Bh, int ldb, int n0, int k0, int tid)
{
#pragma unroll
    for (int it = 0; it < 2; ++it) {           // A: 128 rows x 8 x16B
        int id = tid + it * 512;
        int r  = id >> 3;
        int cw = id & 7;
        cp_async16(st + (uint32_t)(r * ROW_B + cw * 16),
                   Ah + (size_t)(m0 + r) * lda + k0 + cw * 8);
    }
#pragma unroll
    for (int it = 0; it < 4; ++it) {           // B: 256 rows x 8 x16B
        int id = tid + it * 512;
        int r  = id >> 3;
        int cw = id & 7;
        cp_async16(st + A_TILE_B + (uint32_t)(r * ROW_B + cw * 16),
                   Bh + (size_t)(n0 + r) * ldb + k0 + cw * 8);
    }
}

__device__ __forceinline__ void gemm_mainloop(uint32_t sbase,
    const __half* __restrict__ Ah, int lda, int m0,
    const __half* __restrict__ Bh, int ldb, int n0, int K, int tid,
    uint32_t aoff, uint32_t boff, float acc[2][4][8])
{
    const int nc = K >> 6;
    load_stage_g(sbase, Ah, lda, m0, Bh, ldb, n0, 0, tid);
    CP_COMMIT();
    if (nc > 1) load_stage_g(sbase + STAGE_B, Ah, lda, m0, Bh, ldb, n0, 64, tid);
    CP_COMMIT();

#pragma unroll 1
    for (int c = 0; c < nc; c++) {
        CP_WAIT1();
        __syncthreads();
        int cn = c + 2;
        if (cn < nc)
            load_stage_g(sbase + (uint32_t)(cn % 3) * STAGE_B, Ah, lda, m0, Bh, ldb, n0, cn * 64, tid);
        CP_COMMIT();

        const uint32_t st  = sbase + (uint32_t)(c % 3) * STAGE_B;
        const uint32_t sAh = st, sBh = st + A_TILE_B;
#pragma unroll
        for (int ks = 0; ks < 4; ks++) {
            uint32_t ah[2][4], bh[4][4];
#pragma unroll
            for (int mi = 0; mi < 2; mi++)
                LDSM_X4(ah[mi], sAh + aoff + (uint32_t)(mi * (16 * ROW_B) + ks * 32));
#pragma unroll
            for (int p = 0; p < 4; p++)
                LDSM_X4(bh[p], sBh + boff + (uint32_t)(p * (16 * ROW_B) + ks * 32));
#pragma unroll
            for (int p = 0; p < 4; p++)
#pragma unroll
                for (int mi = 0; mi < 2; mi++) {
                    MMA_F16((acc[mi][p] + 0), ah[mi], bh[p][0], bh[p][1]);
                    MMA_F16((acc[mi][p] + 4), ah[mi], bh[p][2], bh[p][3]);
                }
        }
    }
}

// ============================ fat projection GEMM ===============================
struct GSeg {
    const __half* A; const __half* B; __half* C;
    int lda, ldb, ldc, nx, base, rowbias;
    const float* bias;
};
struct GSegs { GSeg s[6]; };

__global__ __launch_bounds__(512, 1)
void gemm_proj(GSegs segs)
{
    extern __shared__ __align__(16) char smem[];
    const uint32_t sbase = smem_u32(smem);
    const int tid = threadIdx.x, wid = tid >> 5, lane = tid & 31;
    const int bid = blockIdx.x;

    int si = 0;
#pragma unroll
    for (int i = 1; i < 6; i++) if (bid >= segs.s[i].base) si = i;
    const GSeg sg = segs.s[si];
    const int lid = bid - sg.base;
    const int m0 = (lid / sg.nx) * 128;
    const int n0 = (lid % sg.nx) * 256;
    const int wm = wid & 3, wn = wid >> 2;

    const uint32_t aoff = (uint32_t)((wm * 32 + (lane & 15)) * ROW_B + (lane >> 4) * 16);
    const uint32_t boff = (uint32_t)((wn * 64 + ((lane >> 4) & 1) * 8 + (lane & 7)) * ROW_B
                                     + ((lane >> 3) & 1) * 16);

    float acc[2][4][8];
#pragma unroll
    for (int i = 0; i < 2; i++)
#pragma unroll
        for (int j = 0; j < 4; j++)
#pragma unroll
            for (int q = 0; q < 8; q++) acc[i][j][q] = 0.f;

    gemm_mainloop(sbase, sg.A, sg.lda, m0, sg.B, sg.ldb, n0, QDIM, tid, aoff, boff, acc);

#pragma unroll
    for (int mi = 0; mi < 2; mi++) {
        const int r0 = m0 + wm * 32 + mi * 16 + (lane >> 2);
        const int r1 = r0 + 8;
        float rb0 = 0.f, rb1 = 0.f;
        if (sg.rowbias) { rb0 = sg.bias[r0]; rb1 = sg.bias[r1]; }
#pragma unroll
        for (int p = 0; p < 4; p++) {
#pragma unroll
            for (int n8 = 0; n8 < 2; n8++) {
                const int col = n0 + wn * 64 + p * 16 + n8 * 8 + 2 * (lane & 3);
                const float* a4 = acc[mi][p] + n8 * 4;
                float v0 = a4[0], v1 = a4[1], v2 = a4[2], v3 = a4[3];
                if (sg.rowbias) {
                    v0 += rb0; v1 += rb0; v2 += rb1; v3 += rb1;
                } else {
                    float b0 = sg.bias[col], b1 = sg.bias[col + 1];
                    v0 += b0; v1 += b1; v2 += b0; v3 += b1;
                }
                *reinterpret_cast<__half2*>(sg.C + (size_t)r0 * sg.ldc + col) =
                    __halves2half2(__float2half_rn(v0), __float2half_rn(v1));
                *reinterpret_cast<__half2*>(sg.C + (size_t)r1 * sg.ldc + col) =
                    __halves2half2(__float2half_rn(v2), __float2half_rn(v3));
            }
        }
    }
}

// ============================ templated GEMM (scores/PV/FFN) ====================
// MODE 3: f32 *1/rsum[row] | 4: f32 +col-bias
// MODE 5: e = exp(alpha*acc) -> fp16 out; atomicAdd row sums into rsum
template<int MODE>
__global__ __launch_bounds__(512, 1)
void gemm_f16(const __half* __restrict__ Ah, int lda, size_t zsA,
              const __half* __restrict__ Bh, int ldb, size_t zsB,
              int K,
              float* __restrict__ Cf, __half* __restrict__ Ch, int ldc, size_t zsC,
              float alpha, const float* __restrict__ bias,
              float* __restrict__ rsum, int zrs)
{
    extern __shared__ __align__(16) char smem[];
    const uint32_t sbase = smem_u32(smem);
    const int tid = threadIdx.x, wid = tid >> 5, lane = tid & 31;
    const int z = blockIdx.z;
    const int m0 = blockIdx.y * 128, n0 = blockIdx.x * 256;
    const int wm = wid & 3, wn = wid >> 2;

    Ah += (size_t)z * zsA;
    Bh += (size_t)z * zsB;
    if (Cf) Cf += (size_t)z * zsC;
    if (Ch) Ch += (size_t)z * zsC;
    if (rsum) rsum += (size_t)z * zrs;

    const uint32_t aoff = (uint32_t)((wm * 32 + (lane & 15)) * ROW_B + (lane >> 4) * 16);
    const uint32_t boff = (uint32_t)((wn * 64 + ((lane >> 4) & 1) * 8 + (lane & 7)) * ROW_B
                                     + ((lane >> 3) & 1) * 16);

    float acc[2][4][8];
#pragma unroll
    for (int i = 0; i < 2; i++)
#pragma unroll
        for (int j = 0; j < 4; j++)
#pragma unroll
            for (int q = 0; q < 8; q++) acc[i][j][q] = 0.f;

    gemm_mainloop(sbase, Ah, lda, m0, Bh, ldb, n0, K, tid, aoff, boff, acc);

#pragma unroll
    for (int mi = 0; mi < 2; mi++) {
        const int r0 = m0 + wm * 32 + mi * 16 + (lane >> 2);
        const int r1 = r0 + 8;
        float s0 = 1.f, s1 = 1.f;
        if (MODE == 3) { s0 = 1.f / rsum[r0]; s1 = 1.f / rsum[r1]; }
        float rsum0 = 0.f, rsum1 = 0.f;
#pragma unroll
        for (int p = 0; p < 4; p++) {
#pragma unroll
            for (int n8 = 0; n8 < 2; n8++) {
                const int col = n0 + wn * 64 + p * 16 + n8 * 8 + 2 * (lane & 3);
                const float* a4 = acc[mi][p] + n8 * 4;
                float v0 = a4[0], v1 = a4[1], v2 = a4[2], v3 = a4[3];
                if (MODE == 5) {
                    v0 = __expf(v0 * alpha); v1 = __expf(v1 * alpha);
                    v2 = __expf(v2 * alpha); v3 = __expf(v3 * alpha);
                    rsum0 += v0 + v1; rsum1 += v2 + v3;
                    *reinterpret_cast<__half2*>(Ch + (size_t)r0 * ldc + col) =
                        __halves2half2(__float2half_rn(v0), __float2half_rn(v1));
                    *reinterpret_cast<__half2*>(Ch + (size_t)r1 * ldc + col) =
                        __halves2half2(__float2half_rn(v2), __float2half_rn(v3));
                    continue;
                }
                if (MODE == 3) { v0 *= s0; v1 *= s0; v2 *= s1; v3 *= s1; }
                if (MODE == 4) {
                    float b0 = bias[col], b1 = bias[col + 1];
                    v0 += b0; v1 += b1; v2 += b0; v3 += b1;
                }
                *reinterpret_cast<float2*>(Cf + (size_t)r0 * ldc + col) = make_float2(v0, v1);
                *reinterpret_cast<float2*>(Cf + (size_t)r1 * ldc + col) = make_float2(v2, v3);
            }
        }
        if (MODE == 5) {
            rsum0 += __shfl_xor_sync(0xffffffffu, rsum0, 1);
            rsum0 += __shfl_xor_sync(0xffffffffu, rsum0, 2);
            rsum1 += __shfl_xor_sync(0xffffffffu, rsum1, 1);
            rsum1 += __shfl_xor_sync(0xffffffffu, rsum1, 2);
            if ((lane & 3) == 0) {
                atomicAdd(rsum + r0, rsum0);
                atomicAdd(rsum + r1, rsum1);
            }
        }
    }
}

// ============================ aux kernels =======================================
// One flat conversion kernel for feat | key_bank | 7 weights, plus RS zeroing.
// Flat float4 index space (units of float4):
//   [0, 2M)      feat     (2097152)
//   [2M, 6M+2M)  key_bank (4194304) -> ends 6291456
//   [6291456, +7*524288) weights (contiguous dst in g_W_h)
#define FEAT_N4 2097152
#define KB_END  6291456
#define CONV_TOTAL (6291456 + 7 * 524288)   // 9961472

struct ConvArgs {
    const float4* feat; const float4* kb; const float4* w[7];
    __half2* feat_h; __half2* kb_h; __half2* w_h;   // w_h contiguous for all 7
    float* rs;
};

__device__ __forceinline__ void conv_one(const ConvArgs& a, int i)
{
    float4 v;
    __half2* dp;
    if (i < FEAT_N4) {
        v = a.feat[i];
        dp = a.feat_h + 2 * (size_t)i;
    } else if (i < KB_END) {
        int j = i - FEAT_N4;
        v = a.kb[j];
        dp = a.kb_h + 2 * (size_t)j;
    } else {
        int j = i - KB_END;
        int seg = j >> 19;            // /524288
        int off = j & 524287;
        v = a.w[seg][off];
        dp = a.w_h + 2 * (size_t)j;   // dst contiguous across weights
    }
    dp[0] = __halves2half2(__float2half_rn(v.x), __float2half_rn(v.y));
    dp[1] = __halves2half2(__float2half_rn(v.z), __float2half_rn(v.w));
}

__global__ __launch_bounds__(256)
void conv_all_kernel(ConvArgs a)
{
    // block 0 also zeroes rsum (overlapped with conversions elsewhere)
    if (blockIdx.x == 0) {
        for (int j = threadIdx.x; j < 2 * N_ROIS; j += 256) a.rs[j] = 0.f;
    }
    const int stride = gridDim.x * blockDim.x;
    int i = blockIdx.x * blockDim.x + threadIdx.x;
    for (; i + stride < CONV_TOTAL; i += 2 * stride) {
        conv_one(a, i);
        conv_one(a, i + stride);
    }
    if (i < CONV_TOTAL) conv_one(a, i);
}

__global__ __launch_bounds__(256)
void gate_ln_kernel(const float* __restrict__ F,
                    const float* __restrict__ ln_w, const float* __restrict__ ln_b,
                    const float* __restrict__ prelu_a,
                    __half* __restrict__ Xh)
{
    const int row = blockIdx.x;
    const int t = threadIdx.x, lane = t & 31, w = t >> 5;
    const float4 f1 = reinterpret_cast<const float4*>(F + (size_t)row * LATENT)[t];
    const float4 f2 = reinterpret_cast<const float4*>(F + (size_t)(N_ROIS + row) * LATENT)[t];
    float4 c;
    c.x = f1.x * f2.x; c.y = f1.y * f2.y; c.z = f1.z * f2.z; c.w = f1.w * f2.w;

    __shared__ float red[8], mu_sh, var_sh;
    float s = c.x + c.y + c.z + c.w;
#pragma unroll
    for (int off = 16; off > 0; off >>= 1) s += __shfl_xor_sync(0xffffffffu, s, off);
    if (lane == 0) red[w] = s;
    __syncthreads();
    if (t == 0) {
        float ss = 0.f;
#pragma unroll
        for (int i = 0; i < 8; i++) ss += red[i];
        mu_sh = ss * (1.f / LATENT);
    }
    __syncthreads();
    const float mu = mu_sh;
    float dx = c.x - mu, dy = c.y - mu, dz = c.z - mu, dw = c.w - mu;
    float sq = dx * dx + dy * dy + dz * dz + dw * dw;
#pragma unroll
    for (int off = 16; off > 0; off >>= 1) sq += __shfl_xor_sync(0xffffffffu, sq, off);
    __syncthreads();
    if (lane == 0) red[w] = sq;
    __syncthreads();
    if (t == 0) {
        float ss = 0.f;
#pragma unroll
        for (int i = 0; i < 8; i++) ss += red[i];
        var_sh = ss * (1.f / LATENT);
    }
    __syncthreads();
    const float inv = rsqrtf(var_sh + LN_EPS);
    const float slope = prelu_a[0];
    const float4 wv = reinterpret_cast<const float4*>(ln_w)[t];
    const float4 bv = reinterpret_cast<const float4*>(ln_b)[t];
    float4 x;
    x.x = dx * inv * wv.x + bv.x;  x.y = dy * inv * wv.y + bv.y;
    x.z = dz * inv * wv.z + bv.z;  x.w = dw * inv * wv.w + bv.w;
    x.x = x.x >= 0.f ? x.x : slope * x.x;
    x.y = x.y >= 0.f ? x.y : slope * x.y;
    x.z = x.z >= 0.f ? x.z : slope * x.z;
    x.w = x.w >= 0.f ? x.w : slope * x.w;

    __half2* hp = reinterpret_cast<__half2*>(Xh + (size_t)row * LATENT);
    hp[2 * t + 0] = __halves2half2(__float2half_rn(x.x), __float2half_rn(x.y));
    hp[2 * t + 1] = __halves2half2(__float2half_rn(x.z), __float2half_rn(x.w));
}

// ============================ launch ============================================
static float* symf(const void* s) { void* p; cudaGetSymbolAddress(&p, s); return (float*)p; }
static __half* symh(const void* s) { void* p; cudaGetSymbolAddress(&p, s); return (__half*)p; }

extern "C" void kernel_launch(void* const* d_in, const int* in_sizes, int n_in,
                              void* d_out, int out_size)
{
    const float* feat     = (const float*)d_in[0];
    const float* key_bank = (const float*)d_in[1];
    const float* Wc1 = (const float*)d_in[2];  const float* bc1 = (const float*)d_in[3];
    const float* Wc2 = (const float*)d_in[4];  const float* bc2 = (const float*)d_in[5];
    const float* Wc3 = (const float*)d_in[6];  const float* bc3 = (const float*)d_in[7];
    const float* Wd1 = (const float*)d_in[8];  const float* bd1 = (const float*)d_in[9];
    const float* Wd2 = (const float*)d_in[10]; const float* bd2 = (const float*)d_in[11];
    const float* Wd3 = (const float*)d_in[12]; const float* bd3 = (const float*)d_in[13];
    const float* ln_w = (const float*)d_in[14];
    const float* ln_b = (const float*)d_in[15];
    const float* prelu_a = (const float*)d_in[16];
    const float* Wffn = (const float*)d_in[17];
    const float* bffn = (const float*)d_in[18];
    float* out = (float*)d_out;

    __half *feat_h = symh(&g_feat_h);
    __half *kb_h = symh(&g_kb_h);
    __half *W_h = symh(&g_W_h);
    __half *Q_h = symh(&g_Q_h);
    __half *K_h = symh(&g_K_h);
    __half *Vt_h = symh(&g_Vt_h);
    __half *E_h = symh(&g_E_h);
    __half *X_h = symh(&g_X_h);
    float *F = symf(&g_F), *RS = symf(&g_rsum);

    cudaFuncSetAttribute(gemm_proj,   cudaFuncAttributeMaxDynamicSharedMemorySize, SMEM_G);
    cudaFuncSetAttribute(gemm_f16<3>, cudaFuncAttributeMaxDynamicSharedMemorySize, SMEM_G);
    cudaFuncSetAttribute(gemm_f16<4>, cudaFuncAttributeMaxDynamicSharedMemorySize, SMEM_G);
    cudaFuncSetAttribute(gemm_f16<5>, cudaFuncAttributeMaxDynamicSharedMemorySize, SMEM_G);

    const dim3 blk(256);
    const dim3 blkG(512);

    // ---- one conversion launch for inputs + all weights (+ RS zero)
    ConvArgs ca;
    ca.feat = (const float4*)feat;
    ca.kb   = (const float4*)key_bank;
    const float* Ws[7] = { Wc1, Wd1, Wc2, Wd2, Wc3, Wd3, Wffn };
    for (int i = 0; i < 7; i++) ca.w[i] = (const float4*)Ws[i];
    ca.feat_h = (__half2*)feat_h;
    ca.kb_h   = (__half2*)kb_h;
    ca.w_h    = (__half2*)W_h;
    ca.rs     = RS;
    conv_all_kernel<<<1480, blk>>>(ca);

    const size_t QO = (size_t)N_ROIS * LATENT;
    const size_t KO = (size_t)N_BANK * LATENT;
    const size_t VO = (size_t)LATENT * N_BANK;
    const size_t SO = (size_t)N_ROIS * N_BANK;

    // ---- fat projection launch: Q b0/b1, K b0/b1, Vt b0/b1 (1280 CTAs)
    GSegs gs;
    gs.s[0] = { feat_h, W_h + 0 * WSZ, Q_h,      QDIM, QDIM, LATENT, 4,    0, 0, bc1 };
    gs.s[1] = { feat_h, W_h + 1 * WSZ, Q_h + QO, QDIM, QDIM, LATENT, 4,  128, 0, bd1 };
    gs.s[2] = { kb_h, W_h + 2 * WSZ, K_h,      DIM_IN, DIM_IN, LATENT, 4,  256, 0, bc2 };
    gs.s[3] = { kb_h, W_h + 3 * WSZ, K_h + KO, DIM_IN, DIM_IN, LATENT, 4,  512, 0, bd2 };
    gs.s[4] = { W_h + 4 * WSZ, kb_h, Vt_h,      DIM_IN, DIM_IN, N_BANK, 32,  768, 1, bc3 };
    gs.s[5] = { W_h + 5 * WSZ, kb_h, Vt_h + VO, DIM_IN, DIM_IN, N_BANK, 32, 1024, 1, bd3 };
    gemm_proj<<<1280, blkG, SMEM_G>>>(gs);

    // ---- scores + exp fused, both branches
    gemm_f16<5><<<dim3(32, 32, 2), blkG, SMEM_G>>>(Q_h, LATENT, QO,
        K_h, LATENT, KO, LATENT, nullptr, E_h, N_BANK, SO, 0.03125f, nullptr, RS, N_ROIS);

    // ---- PV, both branches
    gemm_f16<3><<<dim3(4, 32, 2), blkG, SMEM_G>>>(E_h, N_BANK, SO,
        Vt_h, N_BANK, VO, N_BANK, F, nullptr, LATENT, QO, 0.f, nullptr, RS, N_ROIS);

    // ---- gate + LN + PReLU -> X
    gate_ln_kernel<<<N_ROIS, blk>>>(F, ln_w, ln_b, prelu_a, X_h);

    // ---- FFN (1-term)
    gemm_f16<4><<<dim3(8, 32, 1), blkG, SMEM_G>>>(X_h, LATENT, 0,
        W_h + 6 * WSZ, LATENT, 0, LATENT, out, nullptr, DIM_IN, 0, 0.f, bffn, nullptr, 0);
}